// round 3
// baseline (speedup 1.0000x reference)
#include <cuda_runtime.h>

#define NN 50000
#define NE 800000
#define INDIM 64
#define HID 128
#define NL 4
#define NG 128
#define BN_EPS 1e-5f

// ---------------- scratch (device globals; no allocation allowed) ----------------
__device__ float  g_h[NN * HID];      // node features
__device__ float  g_aggr[NN * HID];   // edge aggregation / reused as z
__device__ float  g_z1[NN * HID];     // hidden of conv MLP
__device__ float  g_vn[NG * HID];
__device__ float  g_vnup[NG * HID];
__device__ double g_bn_sum[HID];
__device__ double g_bn_sqs[HID];
__device__ int    g_deg[NN];
__device__ int    g_rowptr[NN + 1];
__device__ int    g_cursor[NN];
__device__ int    g_srcs[NE];         // src node id, CSR-ordered by dst
__device__ float2 g_ea2[NE];          // edge_attr, CSR-ordered by dst
__device__ int    g_part[128];
__device__ int    g_cnt[NG];

// ---------------- small utility kernels ----------------
__global__ void k_zero0() {
    int i = blockIdx.x * blockDim.x + threadIdx.x;
    if (i < NN) g_deg[i] = 0;
    if (i < NG * HID) g_vn[i] = 0.f;
    if (i < NG) g_cnt[i] = 0;
}

__global__ void k_zstats() {
    int i = blockIdx.x * blockDim.x + threadIdx.x;
    if (i < NG * HID) g_vnup[i] = 0.f;
    if (i < HID) { g_bn_sum[i] = 0.0; g_bn_sqs[i] = 0.0; }
}

__global__ void k_deg(const int* __restrict__ dst) {
    int j = blockIdx.x * blockDim.x + threadIdx.x;
    if (j < NE) atomicAdd(&g_deg[dst[j]], 1);
}

__global__ void k_scan1() {
    __shared__ int s[512];
    int t = threadIdx.x;
    int i = blockIdx.x * 512 + t;
    int v = (i < NN) ? g_deg[i] : 0;
    s[t] = v;
    __syncthreads();
    for (int off = 1; off < 512; off <<= 1) {
        int x = (t >= off) ? s[t - off] : 0;
        __syncthreads();
        s[t] += x;
        __syncthreads();
    }
    if (i < NN) g_rowptr[i + 1] = s[t];
    if (t == 511) g_part[blockIdx.x] = s[511];
}

__global__ void k_scan2(int nb) {
    __shared__ int s[128];
    int t = threadIdx.x;
    s[t] = (t < nb) ? g_part[t] : 0;
    __syncthreads();
    for (int off = 1; off < 128; off <<= 1) {
        int v = (t >= off) ? s[t - off] : 0;
        __syncthreads();
        s[t] += v;
        __syncthreads();
    }
    if (t < nb) g_part[t] = (t == 0) ? 0 : s[t - 1];
}

__global__ void k_scan3() {
    int i = blockIdx.x * blockDim.x + threadIdx.x;
    if (i < NN) {
        int b = i >> 9;
        int val = g_rowptr[i + 1] + g_part[b];
        g_rowptr[i + 1] = val;
        g_cursor[i] = val - g_deg[i];   // exclusive start = rowptr[i]
    }
    if (i == 0) g_rowptr[0] = 0;
}

// fill CSR, pre-gathering src ids and edge attrs into CSR order
__global__ void k_fill(const int* __restrict__ dst, const int* __restrict__ src,
                       const float* __restrict__ ea) {
    int j = blockIdx.x * blockDim.x + threadIdx.x;
    if (j < NE) {
        int d = dst[j];
        int pos = atomicAdd(&g_cursor[d], 1);
        g_srcs[pos] = src[j];
        g_ea2[pos]  = ((const float2*)ea)[j];
    }
}

__global__ void k_cnt(const int* __restrict__ batch) {
    __shared__ int hist[NG];
    int t = threadIdx.x;
    if (t < NG) hist[t] = 0;
    __syncthreads();
    for (int i = blockIdx.x * blockDim.x + t; i < NN; i += gridDim.x * blockDim.x)
        atomicAdd(&hist[batch[i]], 1);
    __syncthreads();
    if (t < NG) atomicAdd(&g_cnt[t], hist[t]);
}

// ---------------- input GEMM: h = x @ W_in + b_in  (K=64) ----------------
#define GR 64
#define GT 256

__global__ __launch_bounds__(GT) void k_gemm_in(const float* __restrict__ x,
                                                const float* __restrict__ W,
                                                const float* __restrict__ B) {
    __shared__ float Ws[INDIM * HID];   // 32 KB
    __shared__ float As[GR * INDIM];    // 16 KB
    int t = threadIdx.x;
    int tx = t & 31, ty = t >> 5;
    int row0 = blockIdx.x * GR;

    for (int i = t; i < INDIM * HID / 4; i += GT)
        ((float4*)Ws)[i] = ((const float4*)W)[i];
    for (int i = t; i < GR * INDIM / 4; i += GT) {
        int r = i >> 4, kc = i & 15;
        int gr = row0 + r;
        ((float4*)As)[i] = (gr < NN) ? ((const float4*)x)[gr * (INDIM / 4) + kc]
                                     : make_float4(0.f, 0.f, 0.f, 0.f);
    }
    __syncthreads();

    float acc[8][4];
#pragma unroll
    for (int i = 0; i < 8; i++)
#pragma unroll
        for (int j = 0; j < 4; j++) acc[i][j] = 0.f;
    int r0 = ty * 8;

#pragma unroll 4
    for (int k = 0; k < INDIM; k++) {
        float4 w = ((float4*)Ws)[k * 32 + tx];
#pragma unroll
        for (int i = 0; i < 8; i++) {
            float a = As[(r0 + i) * INDIM + k];
            acc[i][0] += a * w.x; acc[i][1] += a * w.y;
            acc[i][2] += a * w.z; acc[i][3] += a * w.w;
        }
    }
    float4 bb = ((const float4*)B)[tx];
#pragma unroll
    for (int i = 0; i < 8; i++) {
        int gr = row0 + r0 + i;
        if (gr < NN) {
            float4 o;
            o.x = acc[i][0] + bb.x; o.y = acc[i][1] + bb.y;
            o.z = acc[i][2] + bb.z; o.w = acc[i][3] + bb.w;
            ((float4*)g_h)[gr * 32 + tx] = o;
        }
    }
}

// ---------------- main 128x128 GEMMs ----------------
// MODE 0: z1 = relu((h + aggr) @ W1 + b1)
// MODE 1: z  = z1 @ W2 + b2 (into g_aggr) + column sum/sumsq stats (double)
#define SMEM_SZ ((HID * HID + GR * HID) * 4)

template <int MODE>
__global__ __launch_bounds__(GT) void k_gemm128(const float* __restrict__ W,
                                                const float* __restrict__ B) {
    extern __shared__ float sm[];
    float* Ws = sm;                // 64 KB
    float* As = sm + HID * HID;    // 32 KB
    int t = threadIdx.x;
    int tx = t & 31, ty = t >> 5;
    int row0 = blockIdx.x * GR;

    for (int i = t; i < HID * HID / 4; i += GT)
        ((float4*)Ws)[i] = ((const float4*)W)[i];
    for (int i = t; i < GR * HID / 4; i += GT) {
        int r = i >> 5, kc = i & 31;
        int gr = row0 + r;
        float4 v = make_float4(0.f, 0.f, 0.f, 0.f);
        if (gr < NN) {
            if (MODE == 0) {
                float4 hv = ((const float4*)g_h)[gr * 32 + kc];
                float4 av = ((const float4*)g_aggr)[gr * 32 + kc];
                v.x = hv.x + av.x; v.y = hv.y + av.y;
                v.z = hv.z + av.z; v.w = hv.w + av.w;
            } else {
                v = ((const float4*)g_z1)[gr * 32 + kc];
            }
        }
        ((float4*)As)[i] = v;
    }
    __syncthreads();

    float acc[8][4];
#pragma unroll
    for (int i = 0; i < 8; i++)
#pragma unroll
        for (int j = 0; j < 4; j++) acc[i][j] = 0.f;
    int r0 = ty * 8;

#pragma unroll 4
    for (int k = 0; k < HID; k++) {
        float4 w = ((float4*)Ws)[k * 32 + tx];
#pragma unroll
        for (int i = 0; i < 8; i++) {
            float a = As[(r0 + i) * HID + k];
            acc[i][0] += a * w.x; acc[i][1] += a * w.y;
            acc[i][2] += a * w.z; acc[i][3] += a * w.w;
        }
    }

    float4 bb = ((const float4*)B)[tx];
#pragma unroll
    for (int i = 0; i < 8; i++) {
        acc[i][0] += bb.x; acc[i][1] += bb.y;
        acc[i][2] += bb.z; acc[i][3] += bb.w;
    }

    if (MODE == 0) {
#pragma unroll
        for (int i = 0; i < 8; i++) {
            int gr = row0 + r0 + i;
            if (gr < NN) {
                float4 o;
                o.x = fmaxf(acc[i][0], 0.f); o.y = fmaxf(acc[i][1], 0.f);
                o.z = fmaxf(acc[i][2], 0.f); o.w = fmaxf(acc[i][3], 0.f);
                ((float4*)g_z1)[gr * 32 + tx] = o;
            }
        }
    } else {
        double ls[4] = {0, 0, 0, 0}, lq[4] = {0, 0, 0, 0};
#pragma unroll
        for (int i = 0; i < 8; i++) {
            int gr = row0 + r0 + i;
            if (gr < NN) {
                float4 o;
                o.x = acc[i][0]; o.y = acc[i][1]; o.z = acc[i][2]; o.w = acc[i][3];
                ((float4*)g_aggr)[gr * 32 + tx] = o;
#pragma unroll
                for (int j = 0; j < 4; j++) {
                    double d = (double)acc[i][j];
                    ls[j] += d; lq[j] += d * d;
                }
            }
        }
        __syncthreads();                     // done reading As, reuse as stats
        double* ssum = (double*)As;          // 128 doubles
        double* ssq  = ssum + HID;           // 128 doubles
        if (t < HID) { ssum[t] = 0.0; ssq[t] = 0.0; }
        __syncthreads();
#pragma unroll
        for (int j = 0; j < 4; j++) {
            atomicAdd(&ssum[tx * 4 + j], ls[j]);
            atomicAdd(&ssq[tx * 4 + j], lq[j]);
        }
        __syncthreads();
        if (t < HID) {
            atomicAdd(&g_bn_sum[t], ssum[t]);
            atomicAdd(&g_bn_sqs[t], ssq[t]);
        }
    }
}

// ---------------- virtual node broadcast: h += vn[batch] ----------------
__global__ void k_addvn(const int* __restrict__ batch) {
    int idx = blockIdx.x * blockDim.x + threadIdx.x;   // over NN*32 float4s
    if (idx >= NN * 32) return;
    int n = idx >> 5, c4 = idx & 31;
    int g = batch[n];
    float4 v = ((const float4*)g_vn)[g * 32 + c4];
    float4 h = ((float4*)g_h)[idx];
    h.x += v.x; h.y += v.y; h.z += v.z; h.w += v.w;
    ((float4*)g_h)[idx] = h;
}

// ---------------- CSR gather: aggr[n] = sum_{e: dst==n} relu(h[src] + e_vec) --------
// Metadata pre-gathered to CSR order (sequential loads); depth-4 software pipeline
// on the indirect h[src] loads (static registers, no dynamic indexing).
#define GA_LOAD(P, HV, AV)                                        \
    do {                                                          \
        int _sn = g_srcs[P];                                      \
        AV = g_ea2[P];                                            \
        HV = ((const float4*)g_h)[_sn * 32 + lane];               \
    } while (0)

#define GA_FMA(HV, AV)                                                          \
    do {                                                                        \
        acc.x += fmaxf(HV.x + fmaf(AV.x, w0.x, fmaf(AV.y, w1.x, b4.x)), 0.f);   \
        acc.y += fmaxf(HV.y + fmaf(AV.x, w0.y, fmaf(AV.y, w1.y, b4.y)), 0.f);   \
        acc.z += fmaxf(HV.z + fmaf(AV.x, w0.z, fmaf(AV.y, w1.z, b4.z)), 0.f);   \
        acc.w += fmaxf(HV.w + fmaf(AV.x, w0.w, fmaf(AV.y, w1.w, b4.w)), 0.f);   \
    } while (0)

__global__ __launch_bounds__(256) void k_gather(const float* __restrict__ We,
                                                const float* __restrict__ be) {
    int n = (blockIdx.x * blockDim.x + threadIdx.x) >> 5;
    int lane = threadIdx.x & 31;
    if (n >= NN) return;
    float4 w0 = ((const float4*)We)[lane];        // row 0 of W_e
    float4 w1 = ((const float4*)We)[32 + lane];   // row 1 of W_e
    float4 b4 = ((const float4*)be)[lane];
    float4 acc = make_float4(0.f, 0.f, 0.f, 0.f);
    int p = g_rowptr[n], e = g_rowptr[n + 1];

    float4 h0, h1, h2, h3;
    float2 a0, a1, a2, a3;
    if (p + 0 < e) GA_LOAD(p + 0, h0, a0);
    if (p + 1 < e) GA_LOAD(p + 1, h1, a1);
    if (p + 2 < e) GA_LOAD(p + 2, h2, a2);
    if (p + 3 < e) GA_LOAD(p + 3, h3, a3);

    while (p + 4 <= e) {
        GA_FMA(h0, a0); GA_FMA(h1, a1); GA_FMA(h2, a2); GA_FMA(h3, a3);
        p += 4;
        if (p + 0 < e) GA_LOAD(p + 0, h0, a0);
        if (p + 1 < e) GA_LOAD(p + 1, h1, a1);
        if (p + 2 < e) GA_LOAD(p + 2, h2, a2);
        if (p + 3 < e) GA_LOAD(p + 3, h3, a3);
    }
    int r = e - p;
    if (r > 0) GA_FMA(h0, a0);
    if (r > 1) GA_FMA(h1, a1);
    if (r > 2) GA_FMA(h2, a2);

    ((float4*)g_aggr)[n * 32 + lane] = acc;
}

// ---------------- BN apply + relu + segment-sum into vnup ----------------
__global__ __launch_bounds__(HID) void k_bn(const int* __restrict__ batch,
                                            const float* __restrict__ bng,
                                            const float* __restrict__ bnb) {
    int c = threadIdx.x;
    int base = blockIdx.x * 64;
    double mu = g_bn_sum[c] / (double)NN;
    double var = g_bn_sqs[c] / (double)NN - mu * mu;
    if (var < 0.0) var = 0.0;
    float scale = bng[c] * rsqrtf((float)var + BN_EPS);
    float shift = bnb[c] - (float)mu * scale;
    float acc = 0.f;
    int gprev = -1;
    for (int r = 0; r < 64; r++) {
        int n = base + r;
        if (n >= NN) break;
        int gb = batch[n];
        float z = g_aggr[n * HID + c];
        float v = fmaxf(fmaf(z, scale, shift), 0.f);
        g_h[n * HID + c] = v;
        if (gb != gprev) {
            if (gprev >= 0) atomicAdd(&g_vnup[gprev * HID + c], acc);
            acc = 0.f;
            gprev = gb;
        }
        acc += v;
    }
    if (gprev >= 0) atomicAdd(&g_vnup[gprev * HID + c], acc);
}

// ---------------- virtual node MLP: vn += mlp(vnup) ----------------
__global__ __launch_bounds__(HID) void k_vnmlp(const float* __restrict__ W1,
                                               const float* __restrict__ b1,
                                               const float* __restrict__ W2,
                                               const float* __restrict__ b2) {
    int g = blockIdx.x, c = threadIdx.x;
    __shared__ float u[HID], tt[HID];
    u[c] = g_vnup[g * HID + c];
    __syncthreads();
    float a = b1[c];
#pragma unroll 4
    for (int k = 0; k < HID; k++) a = fmaf(u[k], W1[k * HID + c], a);
    tt[c] = fmaxf(a, 0.f);
    __syncthreads();
    float o = b2[c];
#pragma unroll 4
    for (int k = 0; k < HID; k++) o = fmaf(tt[k], W2[k * HID + c], o);
    g_vn[g * HID + c] += o;
}

// ---------------- classifier ----------------
__global__ __launch_bounds__(HID) void k_cls(const float* __restrict__ W1,
                                             const float* __restrict__ b1,
                                             const float* __restrict__ W2,
                                             const float* __restrict__ b2,
                                             float* __restrict__ out) {
    int g = blockIdx.x, c = threadIdx.x;
    __shared__ float u[HID], tt[HID], red[HID];
    float cnt = fmaxf((float)g_cnt[g], 1.f);
    u[c] = g_vnup[g * HID + c] / cnt;
    __syncthreads();
    float a = b1[c];
#pragma unroll 4
    for (int k = 0; k < HID; k++) a = fmaf(u[k], W1[k * HID + c], a);
    tt[c] = fmaxf(a, 0.f);
    __syncthreads();
    red[c] = tt[c] * W2[c];
    __syncthreads();
    for (int s = 64; s > 0; s >>= 1) {
        if (c < s) red[c] += red[c + s];
        __syncthreads();
    }
    if (c == 0) out[g] = red[0] + b2[0];
}

// ---------------- host ----------------
extern "C" void kernel_launch(void* const* d_in, const int* in_sizes, int n_in,
                              void* d_out, int out_size) {
    const float *x, *ea, *W_in, *b_in, *W_e, *b_e, *cW1, *cb1, *cW2, *cb2;
    const float *bng, *bnb, *vW1, *vb1, *vW2, *vb2, *clW1, *clb1, *clW2, *clb2;
    const int *ei, *batch;

    if (in_sizes[2] == 2 * NE) {
        // setup_inputs dict order
        x    = (const float*)d_in[0];  ea   = (const float*)d_in[1];
        ei   = (const int*)d_in[2];    batch= (const int*)d_in[3];
        W_in = (const float*)d_in[4];  b_in = (const float*)d_in[5];
        W_e  = (const float*)d_in[6];  b_e  = (const float*)d_in[7];
        cW1  = (const float*)d_in[8];  cb1  = (const float*)d_in[9];
        cW2  = (const float*)d_in[10]; cb2  = (const float*)d_in[11];
        bng  = (const float*)d_in[12]; bnb  = (const float*)d_in[13];
        vW1  = (const float*)d_in[14]; vb1  = (const float*)d_in[15];
        vW2  = (const float*)d_in[16]; vb2  = (const float*)d_in[17];
        clW1 = (const float*)d_in[18]; clb1 = (const float*)d_in[19];
        clW2 = (const float*)d_in[20]; clb2 = (const float*)d_in[21];
    } else {
        // reference() argument order
        x    = (const float*)d_in[0];  ea   = (const float*)d_in[1];
        W_in = (const float*)d_in[2];  b_in = (const float*)d_in[3];
        W_e  = (const float*)d_in[4];  b_e  = (const float*)d_in[5];
        cW1  = (const float*)d_in[6];  cb1  = (const float*)d_in[7];
        cW2  = (const float*)d_in[8];  cb2  = (const float*)d_in[9];
        bng  = (const float*)d_in[10]; bnb  = (const float*)d_in[11];
        vW1  = (const float*)d_in[12]; vb1  = (const float*)d_in[13];
        vW2  = (const float*)d_in[14]; vb2  = (const float*)d_in[15];
        clW1 = (const float*)d_in[16]; clb1 = (const float*)d_in[17];
        clW2 = (const float*)d_in[18]; clb2 = (const float*)d_in[19];
        ei   = (const int*)d_in[20];   batch= (const int*)d_in[21];
    }
    const int* src = ei;
    const int* dst = ei + NE;

    cudaFuncSetAttribute(k_gemm128<0>, cudaFuncAttributeMaxDynamicSharedMemorySize, SMEM_SZ);
    cudaFuncSetAttribute(k_gemm128<1>, cudaFuncAttributeMaxDynamicSharedMemorySize, SMEM_SZ);

    // CSR build + init (every call; fully inside the captured graph)
    k_zero0<<<(NN + 255) / 256, 256>>>();
    k_deg<<<(NE + 255) / 256, 256>>>(dst);
    k_scan1<<<(NN + 511) / 512, 512>>>();
    k_scan2<<<1, 128>>>((NN + 511) / 512);
    k_scan3<<<(NN + 255) / 256, 256>>>();
    k_fill<<<(NE + 255) / 256, 256>>>(dst, src, ea);
    k_gemm_in<<<(NN + GR - 1) / GR, GT>>>(x, W_in, b_in);
    k_cnt<<<64, 256>>>(batch);

    for (int i = 0; i < NL; i++) {
        if (i > 0) k_addvn<<<(NN * 32 + 255) / 256, 256>>>(batch);
        k_zstats<<<64, 256>>>();
        k_gather<<<(NN * 32 + 255) / 256, 256>>>(W_e, b_e);
        k_gemm128<0><<<(NN + GR - 1) / GR, GT, SMEM_SZ>>>(cW1 + i * HID * HID, cb1 + i * HID);
        k_gemm128<1><<<(NN + GR - 1) / GR, GT, SMEM_SZ>>>(cW2 + i * HID * HID, cb2 + i * HID);
        k_bn<<<(NN + 63) / 64, HID>>>(batch, bng + i * HID, bnb + i * HID);
        if (i < NL - 1) k_vnmlp<<<NG, HID>>>(vW1, vb1, vW2, vb2);
    }
    k_cls<<<NG, HID>>>(clW1, clb1, clW2, clb2, (float*)d_out);
}